// round 12
// baseline (speedup 1.0000x reference)
#include <cuda_runtime.h>
#include <cuda_bf16.h>
#include <math.h>
#include <stdint.h>

// Problem constants
#define NN    20000
#define DEG   16
#define F     128
#define G4    512
#define TILE  64
#define NT    256

// ---------------- proj kernel layout (unchanged, tf32) ----------------
#define PH    132
#define PW    68
#define P_SH_HS 0
#define P_SH_WC (TILE*PH + TILE*17)            // 9536
#define P_SMEM_FLOATS (P_SH_WC + G4*PW)        // 44352
#define P_SMEM_BYTES  (P_SMEM_FLOATS*4)        // 177408

// ---------------- rec kernel (4-CTA cluster) layout, u32 units -----------
#define PHS   68      // Hs pitch (u32 bf16x2 rows)
#define PWC   68      // Wc pitch (u32)
#define PGB   140     // Gb pitch (floats); banks 12*gid+tig -> conflict-free
#define R_NB  0                                // 64*17 ints = 1088
#define R_HS  1088                             // 2 x 64 x PHS = 8704
#define R_WC  (R_HS + 2*TILE*PHS)              // 9792
#define R_GB  (R_WC + 128*PWC)                 // 18496
#define R_TOTAL (R_GB + TILE*PGB)              // 27456 u32
#define R_BYTES (R_TOTAL*4)                    // 109824 B -> 2 CTAs/SM

__device__ float g_P [(size_t)NN * G4];   // projections + bias (fp32, exact)
__device__ float g_H1[(size_t)NN * F];    // layer-1 output

// ---------------- helpers ----------------
__device__ __forceinline__ uint32_t f2tf(float f) {
    uint32_t u; asm("cvt.rna.tf32.f32 %0, %1;" : "=r"(u) : "f"(f)); return u;
}
__device__ __forceinline__ uint32_t packbf(float lo, float hi) {
    uint32_t r; asm("cvt.rn.bf16x2.f32 %0, %1, %2;" : "=r"(r) : "f"(hi), "f"(lo));
    return r;
}
__device__ __forceinline__ void mma8(float4& d, uint32_t a0, uint32_t a1, uint32_t a2,
                                     uint32_t a3, uint32_t b0, uint32_t b1) {
    asm volatile(
        "mma.sync.aligned.m16n8k8.row.col.f32.tf32.tf32.f32 "
        "{%0,%1,%2,%3}, {%4,%5,%6,%7}, {%8,%9}, {%0,%1,%2,%3};"
        : "+f"(d.x), "+f"(d.y), "+f"(d.z), "+f"(d.w)
        : "r"(a0), "r"(a1), "r"(a2), "r"(a3), "r"(b0), "r"(b1));
}
__device__ __forceinline__ void mma16(float4& d, uint32_t a0, uint32_t a1, uint32_t a2,
                                      uint32_t a3, uint32_t b0, uint32_t b1) {
    asm volatile(
        "mma.sync.aligned.m16n8k16.row.col.f32.bf16.bf16.f32 "
        "{%0,%1,%2,%3}, {%4,%5,%6,%7}, {%8,%9}, {%0,%1,%2,%3};"
        : "+f"(d.x), "+f"(d.y), "+f"(d.z), "+f"(d.w)
        : "r"(a0), "r"(a1), "r"(a2), "r"(a3), "r"(b0), "r"(b1));
}
__device__ __forceinline__ float sigm_f(float x) {
    float y, h = 0.5f * x;
    asm("tanh.approx.f32 %0, %1;" : "=f"(y) : "f"(h));
    return fmaf(0.5f, y, 0.5f);
}
__device__ __forceinline__ float tanh_f(float x) {
    float y; asm("tanh.approx.f32 %0, %1;" : "=f"(y) : "f"(x)); return y;
}
__device__ __forceinline__ float sigm_p(float x) { return 1.0f / (1.0f + __expf(-x)); }

__device__ __forceinline__ uint32_t ctarank() {
    uint32_t r; asm("mov.u32 %0, %%cluster_ctarank;" : "=r"(r)); return r;
}
__device__ __forceinline__ uint32_t smem_u32(const void* p) {
    uint32_t a;
    asm("{ .reg .u64 t; cvta.to.shared.u64 t, %1; cvt.u32.u64 %0, t; }" : "=r"(a) : "l"(p));
    return a;
}
__device__ __forceinline__ uint32_t mapa_u32(uint32_t addr, uint32_t rank) {
    uint32_t r; asm("mapa.shared::cluster.u32 %0, %1, %2;" : "=r"(r) : "r"(addr), "r"(rank));
    return r;
}
__device__ __forceinline__ void st_dsmem32(uint32_t addr, uint32_t v) {
    asm volatile("st.shared::cluster.u32 [%0], %1;" :: "r"(addr), "r"(v) : "memory");
}
__device__ __forceinline__ void cp16(uint32_t dst, const void* src) {
    asm volatile("cp.async.cg.shared.global [%0], [%1], 16;" :: "r"(dst), "l"(src));
}
__device__ __forceinline__ void cp_commit() {
    asm volatile("cp.async.commit_group;" ::: "memory");
}
__device__ __forceinline__ void cp_wait0() {
    asm volatile("cp.async.wait_group 0;" ::: "memory");
}
#define CLUSTER_SYNC() do { \
    asm volatile("barrier.cluster.arrive.aligned;" ::: "memory"); \
    asm volatile("barrier.cluster.wait.aligned;" ::: "memory"); } while (0)

// ===========================================================================
// proj: g_P[n][col] = X[n] @ Wih[col] + bih[col] + bhh[col]   (tf32, unchanged)
// ===========================================================================
__device__ __forceinline__ void stage_w_tf32(uint32_t* Wc, const float* __restrict__ W, int k0) {
    for (int idx = threadIdx.x; idx < G4 * 16; idx += NT) {
        int q = idx >> 4, k4 = idx & 15;
        float4 v = *reinterpret_cast<const float4*>(W + (size_t)q * F + k0 + k4 * 4);
        uint4 s;
        s.x = f2tf(v.x); s.y = f2tf(v.y); s.z = f2tf(v.z); s.w = f2tf(v.w);
        *reinterpret_cast<uint4*>(Wc + q * PW + k4 * 4) = s;
    }
}

__device__ __forceinline__ void gemm64p(float4 (&acc)[4][8], const uint32_t* __restrict__ Wc,
                                        const float* __restrict__ Hs, int kbase,
                                        int gid, int tig, int wslice) {
#pragma unroll
    for (int k8 = 0; k8 < 8; ++k8) {
        uint32_t bb[8][2];
#pragma unroll
        for (int nj = 0; nj < 8; ++nj) {
            const uint32_t* bp = Wc + (wslice + nj * 8 + gid) * PW + k8 * 8 + tig;
            bb[nj][0] = bp[0];
            bb[nj][1] = bp[4];
        }
#pragma unroll
        for (int mi = 0; mi < 4; ++mi) {
            const float* ap = Hs + (mi * 16 + gid) * PH + kbase + k8 * 8 + tig;
            uint32_t a0 = f2tf(ap[0]);
            uint32_t a1 = f2tf(ap[8 * PH]);
            uint32_t a2 = f2tf(ap[4]);
            uint32_t a3 = f2tf(ap[8 * PH + 4]);
#pragma unroll
            for (int nj = 0; nj < 8; ++nj)
                mma8(acc[mi][nj], a0, a1, a2, a3, bb[nj][0], bb[nj][1]);
        }
    }
}

__global__ void __launch_bounds__(NT, 1)
proj_kernel(const float* __restrict__ Xin, int useH1,
            const float* __restrict__ Wih,
            const float* __restrict__ bih, const float* __restrict__ bhh) {
    extern __shared__ float smem[];
    float* Hs = smem + P_SH_HS;
    uint32_t* Wc = reinterpret_cast<uint32_t*>(smem + P_SH_WC);

    const float* X = useH1 ? g_H1 : Xin;
    const int tid = threadIdx.x, lane = tid & 31, w = tid >> 5;
    const int gid = lane >> 2, tig = lane & 3;
    const int tile0 = blockIdx.x * TILE;

    for (int idx = tid; idx < TILE * 32; idx += NT) {
        int r = idx >> 5, c4 = idx & 31;
        int n = tile0 + r;
        float4 v = make_float4(0.f, 0.f, 0.f, 0.f);
        if (n < NN) v = *reinterpret_cast<const float4*>(X + (size_t)n * F + c4 * 4);
        *reinterpret_cast<float4*>(Hs + r * PH + c4 * 4) = v;
    }

    float4 acc[4][8];
#pragma unroll
    for (int nj = 0; nj < 8; ++nj) {
        int col = w * 64 + nj * 8 + 2 * tig;
        float b0 = __ldg(bih + col) + __ldg(bhh + col);
        float b1 = __ldg(bih + col + 1) + __ldg(bhh + col + 1);
#pragma unroll
        for (int mi = 0; mi < 4; ++mi) acc[mi][nj] = make_float4(b0, b1, b0, b1);
    }

#pragma unroll 1
    for (int c2 = 0; c2 < 2; ++c2) {
        __syncthreads();
        stage_w_tf32(Wc, Wih, c2 * 64);
        __syncthreads();
        gemm64p(acc, Wc, Hs, c2 * 64, gid, tig, w * 64);
    }

#pragma unroll
    for (int mi = 0; mi < 4; ++mi) {
        int r0 = mi * 16 + gid;
        int n0 = tile0 + r0, n1 = n0 + 8;
#pragma unroll
        for (int nj = 0; nj < 8; ++nj) {
            int col = w * 64 + nj * 8 + 2 * tig;
            if (n0 < NN)
                *reinterpret_cast<float2*>(g_P + (size_t)n0 * G4 + col) =
                    make_float2(acc[mi][nj].x, acc[mi][nj].y);
            if (n1 < NN)
                *reinterpret_cast<float2*>(g_P + (size_t)n1 * G4 + col) =
                    make_float2(acc[mi][nj].z, acc[mi][nj].w);
        }
    }
}

// ===========================================================================
// rec: 4-CTA cluster. CTA owns 32 hidden units (128 gate-cols). Whh slice
// resident in smem; P gathered via cp.async into a staging buffer one step
// ahead; h quarters exchanged to all 4 CTAs via DSMEM each step.
//
// Wc column q (0..127): frag=(q>>3)&1, e=q&1, u=(q&7)>>1, wq=q>>4
//   gate = frag*2 + e (i,f,g,o), unit = rank*32 + wq*4 + u
// Thread (w, tig): acc[mi][0].x/.y = (i,f), acc[mi][1].x/.y = (g,o)
//   of unit rank*32 + w*4 + tig at row mi*16+gid (z,w: row +8).
// ===========================================================================
template <int LAYER>
__global__ void __launch_bounds__(NT, 2) __cluster_dims__(4, 1, 1)
rec_kernel(const float* __restrict__ Xin, const int* __restrict__ nbr,
           const float* __restrict__ Whh, const float* __restrict__ Wself,
           const float* __restrict__ Wneigh, const float* __restrict__ bneigh,
           float* __restrict__ out) {
    extern __shared__ uint32_t smemU[];
    int*      Nb  = reinterpret_cast<int*>(smemU + R_NB);
    uint32_t* HsB = smemU + R_HS;                 // 2 x [64][PHS] bf16x2 (full 128 units)
    uint32_t* Wc  = smemU + R_WC;                 // 128 x PWC bf16x2 (Whh slice)
    float*    Gbf = reinterpret_cast<float*>(smemU + R_GB);  // [64][PGB] gather / final-h

    const float* X = (LAYER == 1) ? Xin : g_H1;
    const int tid = threadIdx.x, lane = tid & 31, w = tid >> 5;
    const int gid = lane >> 2, tig = lane & 3;
    const uint32_t rank = ctarank();
    const int tile0 = (blockIdx.x >> 2) * TILE;

    const uint32_t myHsByte = smem_u32(HsB);
    const uint32_t myGbByte = smem_u32(Gbf);
    uint32_t peerHs[3], peerGb[3];
#pragma unroll
    for (int pr = 0; pr < 3; ++pr) {
        peerHs[pr] = mapa_u32(myHsByte, rank ^ (pr + 1));
        peerGb[pr] = mapa_u32(myGbByte, rank ^ (pr + 1));
    }

    // Stage neighbor indices
    for (int idx = tid; idx < TILE * DEG; idx += NT) {
        int r = idx >> 4, t = idx & 15;
        int n = tile0 + r;
        Nb[r * 17 + t] = (n < NN) ? __ldg(nbr + (size_t)n * DEG + t) : 0;
    }
    __syncthreads();

    // Issue gather for t=0: warp handles nodes w*8..w*8+7; lane: gate=lane>>3,
    // chunk j=lane&7. Each node pulls 4 x 128B contiguous gate-slices.
    {
        int gate = lane >> 3, j = lane & 7;
#pragma unroll
        for (int k = 0; k < 8; ++k) {
            int r = w * 8 + k;
            const float* src = g_P + (size_t)Nb[r * 17 + 0] * G4
                             + gate * 128 + (int)rank * 32 + j * 4;
            cp16(myGbByte + (uint32_t)(r * PGB + gate * 32 + j * 4) * 4u, src);
        }
        cp_commit();
    }

    // Stage this CTA's 128-col permuted Whh slice in bf16 (ONCE).
    for (int idx = tid; idx < 128 * 32; idx += NT) {
        int q = idx >> 5, k4 = idx & 31;
        int frag = (q >> 3) & 1, e = q & 1, u = (q & 7) >> 1, wq = q >> 4;
        int oc = (frag * 2 + e) * 128 + (int)rank * 32 + wq * 4 + u;
        float4 v = *reinterpret_cast<const float4*>(Whh + (size_t)oc * F + k4 * 4);
        *reinterpret_cast<uint2*>(Wc + q * PWC + k4 * 2) =
            make_uint2(packbf(v.x, v.y), packbf(v.z, v.w));
    }
    __syncthreads();
    CLUSTER_SYNC();

    const int lu = w * 4 + tig;                 // local unit 0..31
    const int ucol = (int)rank * 16 + w * 2 + (tig >> 1);  // bf16x2 col in Hs

    float2 cst[4];
#pragma unroll
    for (int mi = 0; mi < 4; ++mi) cst[mi] = make_float2(0.f, 0.f);

#pragma unroll 1
    for (int t = 0; t < DEG; ++t) {
        // (a) gather t ready
        cp_wait0();
        __syncthreads();
        // (b) consume staged P into accumulators (conflict-free LDS)
        float4 acc[4][2];
#pragma unroll
        for (int mi = 0; mi < 4; ++mi) {
            const float* g0 = Gbf + (mi * 16 + gid) * PGB + lu;
            const float* g1 = g0 + 8 * PGB;
            acc[mi][0] = make_float4(g0[0], g0[32], g1[0], g1[32]);     // i,f
            acc[mi][1] = make_float4(g0[64], g0[96], g1[64], g1[96]);   // g,o
        }
        // (c) all consumed
        __syncthreads();
        if (t == DEG - 1) CLUSTER_SYNC();   // peers consumed too (Gb reused for final-h)
        // (d) issue gather t+1
        if (t + 1 < DEG) {
            int gate = lane >> 3, j = lane & 7;
#pragma unroll
            for (int k = 0; k < 8; ++k) {
                int r = w * 8 + k;
                const float* src = g_P + (size_t)Nb[r * 17 + t + 1] * G4
                                 + gate * 128 + (int)rank * 32 + j * 4;
                cp16(myGbByte + (uint32_t)(r * PGB + gate * 32 + j * 4) * 4u, src);
            }
            cp_commit();
        }
        // (e) recurrent GEMM on previous h
        if (t > 0) {
            const uint32_t* hb = HsB + ((t - 1) & 1) * (TILE * PHS);
#pragma unroll 4
            for (int k16 = 0; k16 < 8; ++k16) {
                uint32_t bb[2][2];
#pragma unroll
                for (int nj = 0; nj < 2; ++nj) {
                    const uint32_t* bp = Wc + (w * 16 + nj * 8 + gid) * PWC + k16 * 8 + tig;
                    bb[nj][0] = bp[0];
                    bb[nj][1] = bp[4];
                }
#pragma unroll
                for (int mi = 0; mi < 4; ++mi) {
                    const uint32_t* ap = hb + (mi * 16 + gid) * PHS + k16 * 8 + tig;
                    uint32_t a0 = ap[0], a1 = ap[8 * PHS], a2 = ap[4], a3 = ap[8 * PHS + 4];
                    mma16(acc[mi][0], a0, a1, a2, a3, bb[0][0], bb[0][1]);
                    mma16(acc[mi][1], a0, a1, a2, a3, bb[1][0], bb[1][1]);
                }
            }
        }
        // (f) LSTM cell: thread owns i,f,g,o of one unit, 8 cells (4 mi x 2 rows)
        uint32_t* hw = HsB + (t & 1) * (TILE * PHS);
        const uint32_t bufOff = ((t & 1) * (TILE * PHS)) << 2;
#pragma unroll
        for (int mi = 0; mi < 4; ++mi) {
            int r0 = mi * 16 + gid, r1 = r0 + 8;
            float4 I = acc[mi][0];    // x=i(r0) y=f(r0) z=i(r1) w=f(r1)
            float4 GO = acc[mi][1];   // x=g(r0) y=o(r0) z=g(r1) w=o(r1)
            float c0 = fmaf(sigm_f(I.y), cst[mi].x, sigm_f(I.x) * tanh_f(GO.x));
            float c1 = fmaf(sigm_f(I.w), cst[mi].y, sigm_f(I.z) * tanh_f(GO.z));
            cst[mi] = make_float2(c0, c1);
            float h0 = sigm_f(GO.y) * tanh_f(c0);
            float h1 = sigm_f(GO.w) * tanh_f(c1);

            if (t < DEG - 1) {
                // pair units 2k,2k+1 across lane^1, even tig stores bf16x2
                float p0 = __shfl_xor_sync(0xffffffffu, h0, 1);
                float p1 = __shfl_xor_sync(0xffffffffu, h1, 1);
                if ((tig & 1) == 0) {
                    uint32_t v0 = packbf(h0, p0);
                    uint32_t v1 = packbf(h1, p1);
                    int o0 = r0 * PHS + ucol, o1 = r1 * PHS + ucol;
                    hw[o0] = v0;
                    hw[o1] = v1;
#pragma unroll
                    for (int pr = 0; pr < 3; ++pr) {
                        st_dsmem32(peerHs[pr] + bufOff + (o0 << 2), v0);
                        st_dsmem32(peerHs[pr] + bufOff + (o1 << 2), v1);
                    }
                }
            } else {
                // final h in fp32 into Gb (all 4 CTAs), col = global unit
                int gu = (int)rank * 32 + lu;
                int o0 = r0 * PGB + gu, o1 = r1 * PGB + gu;
                Gbf[o0] = h0;
                Gbf[o1] = h1;
#pragma unroll
                for (int pr = 0; pr < 3; ++pr) {
                    st_dsmem32(peerGb[pr] + (o0 << 2), __float_as_uint(h0));
                    st_dsmem32(peerGb[pr] + (o1 << 2), __float_as_uint(h1));
                }
            }
        }
        // (g) h exchange complete
        CLUSTER_SYNC();
    }

    // Gbf now holds the full final h (fp32, 128 units, pitch PGB) in every CTA.
    float* Wcf = reinterpret_cast<float*>(Wc);   // epilogue fp32 weights, pitch PH
    const int nl0 = w * 8;

    if (LAYER == 1) {
        // This CTA computes output cols rank*32 + lane (32 cols).
        const int col = (int)rank * 32 + lane;
        float oacc[8];
        {
            float b0 = __ldg(bneigh + col);
#pragma unroll
            for (int i = 0; i < 8; ++i) oacc[i] = b0;
        }
        // self term: X (global) x Wself rows rank*32..+31
        __syncthreads();
        for (int idx = tid; idx < 32 * 32; idx += NT) {
            int row = idx >> 5, k4 = idx & 31;
            *reinterpret_cast<float4*>(Wcf + row * PH + k4 * 4) =
                *reinterpret_cast<const float4*>(Wself + (size_t)((int)rank * 32 + row) * F + k4 * 4);
        }
        __syncthreads();
#pragma unroll 2
        for (int k4 = 0; k4 < 32; ++k4) {
            float4 a[8];
#pragma unroll
            for (int i = 0; i < 8; ++i) {
                int n = tile0 + nl0 + i;
                a[i] = (n < NN) ? *reinterpret_cast<const float4*>(X + (size_t)n * F + k4 * 4)
                                : make_float4(0.f, 0.f, 0.f, 0.f);
            }
            float4 b = *reinterpret_cast<const float4*>(Wcf + lane * PH + k4 * 4);
#pragma unroll
            for (int i = 0; i < 8; ++i)
                oacc[i] = fmaf(a[i].x, b.x, fmaf(a[i].y, b.y,
                          fmaf(a[i].z, b.z, fmaf(a[i].w, b.w, oacc[i]))));
        }
        // neighbor term: final h (fp32 smem) x Wneigh rows rank*32..+31
        __syncthreads();
        for (int idx = tid; idx < 32 * 32; idx += NT) {
            int row = idx >> 5, k4 = idx & 31;
            *reinterpret_cast<float4*>(Wcf + row * PH + k4 * 4) =
                *reinterpret_cast<const float4*>(Wneigh + (size_t)((int)rank * 32 + row) * F + k4 * 4);
        }
        __syncthreads();
#pragma unroll 2
        for (int k4 = 0; k4 < 32; ++k4) {
            float4 a[8];
#pragma unroll
            for (int i = 0; i < 8; ++i)
                a[i] = *reinterpret_cast<const float4*>(Gbf + (nl0 + i) * PGB + k4 * 4);
            float4 b = *reinterpret_cast<const float4*>(Wcf + lane * PH + k4 * 4);
#pragma unroll
            for (int i = 0; i < 8; ++i)
                oacc[i] = fmaf(a[i].x, b.x, fmaf(a[i].y, b.y,
                          fmaf(a[i].z, b.z, fmaf(a[i].w, b.w, oacc[i]))));
        }
#pragma unroll
        for (int i = 0; i < 8; ++i) {
            int n = tile0 + nl0 + i;
            if (n < NN) g_H1[(size_t)n * F + col] = fmaxf(oacc[i], 0.0f);
        }
    } else {
        if (rank == 0) {
            float part[8];
#pragma unroll
            for (int i = 0; i < 8; ++i) part[i] = 0.0f;
#pragma unroll
            for (int uu = 0; uu < 4; ++uu) {
                int u = uu * 32 + lane;
                float wn = __ldg(Wneigh + u);
                float ws = __ldg(Wself + u);
#pragma unroll
                for (int i = 0; i < 8; ++i) {
                    int n = tile0 + nl0 + i;
                    float hx = Gbf[(nl0 + i) * PGB + u];
                    float xx = (n < NN) ? __ldg(X + (size_t)n * F + u) : 0.0f;
                    part[i] = fmaf(hx, wn, fmaf(xx, ws, part[i]));
                }
            }
            float b0 = __ldg(bneigh);
#pragma unroll
            for (int off = 16; off > 0; off >>= 1)
#pragma unroll
                for (int i = 0; i < 8; ++i)
                    part[i] += __shfl_xor_sync(0xffffffffu, part[i], off);
            if (lane == 0) {
#pragma unroll
                for (int i = 0; i < 8; ++i) {
                    int n = tile0 + nl0 + i;
                    if (n < NN) out[n] = sigm_p(part[i] + b0);
                }
            }
        }
    }
}

extern "C" void kernel_launch(void* const* d_in, const int* in_sizes, int n_in,
                              void* d_out, int out_size) {
    const float* x       = (const float*)d_in[0];
    const int*   nbr     = (const int*)  d_in[1];
    const float* Wih1    = (const float*)d_in[2];
    const float* Whh1    = (const float*)d_in[3];
    const float* bih1    = (const float*)d_in[4];
    const float* bhh1    = (const float*)d_in[5];
    const float* Wself1  = (const float*)d_in[6];
    const float* Wneigh1 = (const float*)d_in[7];
    const float* bneigh1 = (const float*)d_in[8];
    const float* Wih2    = (const float*)d_in[9];
    const float* Whh2    = (const float*)d_in[10];
    const float* bih2    = (const float*)d_in[11];
    const float* bhh2    = (const float*)d_in[12];
    const float* Wself2  = (const float*)d_in[13];
    const float* Wneigh2 = (const float*)d_in[14];
    const float* bneigh2 = (const float*)d_in[15];
    float* out = (float*)d_out;

    const int nbp = (NN + TILE - 1) / TILE;   // 313 proj blocks
    const int nbr_grid = nbp * 4;             // 1252 rec CTAs (313 clusters of 4)

    cudaFuncSetAttribute(proj_kernel,   cudaFuncAttributeMaxDynamicSharedMemorySize, P_SMEM_BYTES);
    cudaFuncSetAttribute(rec_kernel<1>, cudaFuncAttributeMaxDynamicSharedMemorySize, R_BYTES);
    cudaFuncSetAttribute(rec_kernel<2>, cudaFuncAttributeMaxDynamicSharedMemorySize, R_BYTES);

    proj_kernel<<<nbp, NT, P_SMEM_BYTES>>>(x, 0, Wih1, bih1, bhh1);
    rec_kernel<1><<<nbr_grid, NT, R_BYTES>>>(x, nbr, Whh1, Wself1, Wneigh1, bneigh1, nullptr);
    proj_kernel<<<nbp, NT, P_SMEM_BYTES>>>(nullptr, 1, Wih2, bih2, bhh2);
    rec_kernel<2><<<nbr_grid, NT, R_BYTES>>>(nullptr, nbr, Whh2, Wself2, Wneigh2, bneigh2, out);
}

// round 13
// speedup vs baseline: 1.2342x; 1.2342x over previous
#include <cuda_runtime.h>
#include <cuda_bf16.h>
#include <math.h>
#include <stdint.h>

// Problem constants
#define NN    20000
#define DEG   16
#define F     128
#define G4    512
#define TILE  64
#define NT    256     // proj threads
#define NTR   512     // rec threads (16 warps, single CTA)

// ---------------- proj kernel layout (tf32) ----------------
#define PH    132
#define PW    68
#define P_SH_HS 0
#define P_SH_WC (TILE*PH + TILE*17)            // 9536
#define P_SMEM_FLOATS (P_SH_WC + G4*PW)        // 44352
#define P_SMEM_BYTES  (P_SMEM_FLOATS*4)        // 177408

// ---------------- rec kernel (single CTA, 512 thr) layout, u32 units -----
#define PHS   68                               // Hs pitch (u32, bf16x2)
#define PWC   68                               // Wc pitch (u32)
#define PE    132                              // fp32 pitch (final h / epilogue W)
#define R_NB  0                                // 64*17 = 1088
#define R_HS  1088                             // 2 x 64 x PHS = 8704
#define R_WC  (R_HS + 2*TILE*PHS)              // 9792
#define R_TOTAL (R_WC + G4*PWC)                // 44608 u32
#define R_BYTES (R_TOTAL*4)                    // 178,432 B -> occ 1

__device__ float g_P [(size_t)NN * G4];   // projections + bias, UNIT-MAJOR: [n][unit*4+gate]
__device__ float g_H1[(size_t)NN * F];    // layer-1 output

// ---------------- helpers ----------------
__device__ __forceinline__ uint32_t f2tf(float f) {
    uint32_t u; asm("cvt.rna.tf32.f32 %0, %1;" : "=r"(u) : "f"(f)); return u;
}
__device__ __forceinline__ uint32_t packbf(float lo, float hi) {
    uint32_t r; asm("cvt.rn.bf16x2.f32 %0, %1, %2;" : "=r"(r) : "f"(hi), "f"(lo));
    return r;
}
__device__ __forceinline__ void mma8(float4& d, uint32_t a0, uint32_t a1, uint32_t a2,
                                     uint32_t a3, uint32_t b0, uint32_t b1) {
    asm volatile(
        "mma.sync.aligned.m16n8k8.row.col.f32.tf32.tf32.f32 "
        "{%0,%1,%2,%3}, {%4,%5,%6,%7}, {%8,%9}, {%0,%1,%2,%3};"
        : "+f"(d.x), "+f"(d.y), "+f"(d.z), "+f"(d.w)
        : "r"(a0), "r"(a1), "r"(a2), "r"(a3), "r"(b0), "r"(b1));
}
__device__ __forceinline__ void mma16(float4& d, uint32_t a0, uint32_t a1, uint32_t a2,
                                      uint32_t a3, uint32_t b0, uint32_t b1) {
    asm volatile(
        "mma.sync.aligned.m16n8k16.row.col.f32.bf16.bf16.f32 "
        "{%0,%1,%2,%3}, {%4,%5,%6,%7}, {%8,%9}, {%0,%1,%2,%3};"
        : "+f"(d.x), "+f"(d.y), "+f"(d.z), "+f"(d.w)
        : "r"(a0), "r"(a1), "r"(a2), "r"(a3), "r"(b0), "r"(b1));
}
__device__ __forceinline__ float sigm_f(float x) {
    float y, h = 0.5f * x;
    asm("tanh.approx.f32 %0, %1;" : "=f"(y) : "f"(h));
    return fmaf(0.5f, y, 0.5f);
}
__device__ __forceinline__ float tanh_f(float x) {
    float y; asm("tanh.approx.f32 %0, %1;" : "=f"(y) : "f"(x)); return y;
}
__device__ __forceinline__ float sigm_p(float x) { return 1.0f / (1.0f + __expf(-x)); }

// ===========================================================================
// proj: g_P[n][unit*4+gate] = X[n] @ Wih[gate*128+unit] + bih + bhh  (tf32)
// ===========================================================================
__device__ __forceinline__ void stage_w_tf32(uint32_t* Wc, const float* __restrict__ W, int k0) {
    for (int idx = threadIdx.x; idx < G4 * 16; idx += NT) {
        int q = idx >> 4, k4 = idx & 15;
        float4 v = *reinterpret_cast<const float4*>(W + (size_t)q * F + k0 + k4 * 4);
        uint4 s;
        s.x = f2tf(v.x); s.y = f2tf(v.y); s.z = f2tf(v.z); s.w = f2tf(v.w);
        *reinterpret_cast<uint4*>(Wc + q * PW + k4 * 4) = s;
    }
}

__device__ __forceinline__ void gemm64p(float4 (&acc)[4][8], const uint32_t* __restrict__ Wc,
                                        const float* __restrict__ Hs, int kbase,
                                        int gid, int tig, int wslice) {
#pragma unroll
    for (int k8 = 0; k8 < 8; ++k8) {
        uint32_t bb[8][2];
#pragma unroll
        for (int nj = 0; nj < 8; ++nj) {
            const uint32_t* bp = Wc + (wslice + nj * 8 + gid) * PW + k8 * 8 + tig;
            bb[nj][0] = bp[0];
            bb[nj][1] = bp[4];
        }
#pragma unroll
        for (int mi = 0; mi < 4; ++mi) {
            const float* ap = Hs + (mi * 16 + gid) * PH + kbase + k8 * 8 + tig;
            uint32_t a0 = f2tf(ap[0]);
            uint32_t a1 = f2tf(ap[8 * PH]);
            uint32_t a2 = f2tf(ap[4]);
            uint32_t a3 = f2tf(ap[8 * PH + 4]);
#pragma unroll
            for (int nj = 0; nj < 8; ++nj)
                mma8(acc[mi][nj], a0, a1, a2, a3, bb[nj][0], bb[nj][1]);
        }
    }
}

__global__ void __launch_bounds__(NT, 1)
proj_kernel(const float* __restrict__ Xin, int useH1,
            const float* __restrict__ Wih,
            const float* __restrict__ bih, const float* __restrict__ bhh) {
    extern __shared__ float smem[];
    float* Hs = smem + P_SH_HS;
    uint32_t* Wc = reinterpret_cast<uint32_t*>(smem + P_SH_WC);

    const float* X = useH1 ? g_H1 : Xin;
    const int tid = threadIdx.x, lane = tid & 31, w = tid >> 5;
    const int gid = lane >> 2, tig = lane & 3;
    const int tile0 = blockIdx.x * TILE;

    for (int idx = tid; idx < TILE * 32; idx += NT) {
        int r = idx >> 5, c4 = idx & 31;
        int n = tile0 + r;
        float4 v = make_float4(0.f, 0.f, 0.f, 0.f);
        if (n < NN) v = *reinterpret_cast<const float4*>(X + (size_t)n * F + c4 * 4);
        *reinterpret_cast<float4*>(Hs + r * PH + c4 * 4) = v;
    }

    float4 acc[4][8];
#pragma unroll
    for (int nj = 0; nj < 8; ++nj) {
        int col = w * 64 + nj * 8 + 2 * tig;
        float b0 = __ldg(bih + col) + __ldg(bhh + col);
        float b1 = __ldg(bih + col + 1) + __ldg(bhh + col + 1);
#pragma unroll
        for (int mi = 0; mi < 4; ++mi) acc[mi][nj] = make_float4(b0, b1, b0, b1);
    }

#pragma unroll 1
    for (int c2 = 0; c2 < 2; ++c2) {
        __syncthreads();
        stage_w_tf32(Wc, Wih, c2 * 64);
        __syncthreads();
        gemm64p(acc, Wc, Hs, c2 * 64, gid, tig, w * 64);
    }

    // Unit-major scatter store: P[n][unit*4 + gate]
#pragma unroll
    for (int mi = 0; mi < 4; ++mi) {
        int r0 = mi * 16 + gid;
        int n0 = tile0 + r0, n1 = n0 + 8;
#pragma unroll
        for (int nj = 0; nj < 8; ++nj) {
            int col = w * 64 + nj * 8 + 2 * tig;
            int gate = col >> 7, unit = col & 127;
            int o0 = unit * 4 + gate, o1 = (unit + 1) * 4 + gate;
            if (n0 < NN) {
                g_P[(size_t)n0 * G4 + o0] = acc[mi][nj].x;
                g_P[(size_t)n0 * G4 + o1] = acc[mi][nj].y;
            }
            if (n1 < NN) {
                g_P[(size_t)n1 * G4 + o0] = acc[mi][nj].z;
                g_P[(size_t)n1 * G4 + o1] = acc[mi][nj].w;
            }
        }
    }
}

// ===========================================================================
// rec: single CTA, 512 threads. Full bf16 Whh resident (136 KB). Warp w owns
// units w*8..w*8+7; Wc col q: w=q>>5, gate=(q>>3)&3, j=q&7 ->
// original row gate*128 + w*8 + j. Thread (tig) holds i,f,g,o of units
// u0=w*8+2tig, u0+1 -> acc[mi][gate] = (u0@r0, u1@r0, u0@r1, u1@r1).
// ===========================================================================
template <int LAYER>
__global__ void __launch_bounds__(NTR, 1)
rec_kernel(const float* __restrict__ Xin, const int* __restrict__ nbr,
           const float* __restrict__ Whh, const float* __restrict__ Wself,
           const float* __restrict__ Wneigh, const float* __restrict__ bneigh,
           float* __restrict__ out) {
    extern __shared__ uint32_t smemU[];
    int*      Nb  = reinterpret_cast<int*>(smemU + R_NB);
    uint32_t* HsB = smemU + R_HS;     // 2 x [64][PHS] bf16x2; fp32 final-h @ pitch PE
    uint32_t* Wc  = smemU + R_WC;     // 512 x PWC bf16x2 (full Whh, permuted)

    const float* X = (LAYER == 1) ? Xin : g_H1;
    const int tid = threadIdx.x, lane = tid & 31, w = tid >> 5;   // w 0..15
    const int gid = lane >> 2, tig = lane & 3;
    const int tile0 = blockIdx.x * TILE;

    // Stage neighbor indices
    for (int idx = tid; idx < TILE * DEG; idx += NTR) {
        int r = idx >> 4, t = idx & 15;
        int n = tile0 + r;
        Nb[r * 17 + t] = (n < NN) ? __ldg(nbr + (size_t)n * DEG + t) : 0;
    }
    // Stage full permuted Whh in bf16 (ONCE)
    for (int idx = tid; idx < G4 * 32; idx += NTR) {
        int q = idx >> 5, k4 = idx & 31;
        int wq = q >> 5, gate = (q >> 3) & 3, j = q & 7;
        int oc = gate * 128 + wq * 8 + j;
        float4 v = *reinterpret_cast<const float4*>(Whh + (size_t)oc * F + k4 * 4);
        *reinterpret_cast<uint2*>(Wc + q * PWC + k4 * 2) =
            make_uint2(packbf(v.x, v.y), packbf(v.z, v.w));
    }
    __syncthreads();

    const int u0 = w * 8 + 2 * tig;          // first of this thread's unit pair
    const int ucol = w * 4 + tig;            // bf16x2 u32 col in Hs

    float4 cst[4];
#pragma unroll
    for (int mi = 0; mi < 4; ++mi) cst[mi] = make_float4(0.f, 0.f, 0.f, 0.f);

#pragma unroll 1
    for (int t = 0; t < DEG; ++t) {
        // Gather P (unit-major): 4 LDG.128 per mi, contiguous per node
        float4 acc[4][4];
#pragma unroll
        for (int mi = 0; mi < 4; ++mi) {
            int r0 = mi * 16 + gid;
            const float* Pa = g_P + (size_t)Nb[r0 * 17 + t] * G4 + u0 * 4;
            const float* Pb = g_P + (size_t)Nb[(r0 + 8) * 17 + t] * G4 + u0 * 4;
            float4 A0 = __ldg(reinterpret_cast<const float4*>(Pa));
            float4 B0 = __ldg(reinterpret_cast<const float4*>(Pa + 4));
            float4 A1 = __ldg(reinterpret_cast<const float4*>(Pb));
            float4 B1 = __ldg(reinterpret_cast<const float4*>(Pb + 4));
            acc[mi][0] = make_float4(A0.x, B0.x, A1.x, B1.x);   // i
            acc[mi][1] = make_float4(A0.y, B0.y, A1.y, B1.y);   // f
            acc[mi][2] = make_float4(A0.z, B0.z, A1.z, B1.z);   // g
            acc[mi][3] = make_float4(A0.w, B0.w, A1.w, B1.w);   // o
        }

        if (t > 0) {
            const uint32_t* hb = HsB + ((t - 1) & 1) * (TILE * PHS);
#pragma unroll 4
            for (int k16 = 0; k16 < 8; ++k16) {
                uint32_t bb[4][2];
#pragma unroll
                for (int nj = 0; nj < 4; ++nj) {
                    const uint32_t* bp = Wc + (w * 32 + nj * 8 + gid) * PWC + k16 * 8 + tig;
                    bb[nj][0] = bp[0];
                    bb[nj][1] = bp[4];
                }
#pragma unroll
                for (int mi = 0; mi < 4; ++mi) {
                    const uint32_t* ap = hb + (mi * 16 + gid) * PHS + k16 * 8 + tig;
                    uint32_t a0 = ap[0], a1 = ap[8 * PHS], a2 = ap[4], a3 = ap[8 * PHS + 4];
#pragma unroll
                    for (int nj = 0; nj < 4; ++nj)
                        mma16(acc[mi][nj], a0, a1, a2, a3, bb[nj][0], bb[nj][1]);
                }
            }
        }

        // Last step overwrites Hs with fp32 final-h spanning both buffers:
        // all warps must be done reading buf[(t-1)&1] first.
        if (t == DEG - 1) __syncthreads();

        uint32_t* hw = HsB + (t & 1) * (TILE * PHS);
#pragma unroll
        for (int mi = 0; mi < 4; ++mi) {
            int r0 = mi * 16 + gid, r1 = r0 + 8;
            float4 I = acc[mi][0], Fg = acc[mi][1], G = acc[mi][2], O = acc[mi][3];
            float4 C = cst[mi];
            float cx = fmaf(sigm_f(Fg.x), C.x, sigm_f(I.x) * tanh_f(G.x));
            float cy = fmaf(sigm_f(Fg.y), C.y, sigm_f(I.y) * tanh_f(G.y));
            float cz = fmaf(sigm_f(Fg.z), C.z, sigm_f(I.z) * tanh_f(G.z));
            float cw = fmaf(sigm_f(Fg.w), C.w, sigm_f(I.w) * tanh_f(G.w));
            cst[mi] = make_float4(cx, cy, cz, cw);
            float h00 = sigm_f(O.x) * tanh_f(cx);   // u0 @ r0
            float h01 = sigm_f(O.y) * tanh_f(cy);   // u1 @ r0
            float h10 = sigm_f(O.z) * tanh_f(cz);   // u0 @ r1
            float h11 = sigm_f(O.w) * tanh_f(cw);   // u1 @ r1

            if (t < DEG - 1) {
                hw[r0 * PHS + ucol] = packbf(h00, h01);
                hw[r1 * PHS + ucol] = packbf(h10, h11);
            } else {
                float* hf = reinterpret_cast<float*>(HsB);
                *reinterpret_cast<float2*>(hf + r0 * PE + u0) = make_float2(h00, h01);
                *reinterpret_cast<float2*>(hf + r1 * PE + u0) = make_float2(h10, h11);
            }
        }
        __syncthreads();
    }

    // HsB = full final h in fp32, pitch PE
    const float* hs0 = reinterpret_cast<const float*>(HsB);
    float* Wcf = reinterpret_cast<float*>(Wc);   // epilogue fp32 weights, pitch PE

    if (LAYER == 1) {
        // Stage Wself (rows 0..127) and Wneigh (rows 128..255), pitch PE
        for (int idx = tid; idx < 256 * 32; idx += NTR) {
            int row = idx >> 5, k4 = idx & 31;
            const float* src = (row < 128) ? (Wself + (size_t)row * F)
                                           : (Wneigh + (size_t)(row - 128) * F);
            *reinterpret_cast<float4*>(Wcf + row * PE + k4 * 4) =
                *reinterpret_cast<const float4*>(src + k4 * 4);
        }
        __syncthreads();

        // Warp w handles 4 nodes; thread covers 4 output cols (uu*32+lane)
        const int nl0 = w * 4;
        float oacc[4][4];
#pragma unroll
        for (int uu = 0; uu < 4; ++uu) {
            float b0 = __ldg(bneigh + uu * 32 + lane);
#pragma unroll
            for (int i = 0; i < 4; ++i) oacc[i][uu] = b0;
        }
#pragma unroll 2
        for (int k4 = 0; k4 < 32; ++k4) {
            float4 a[4], h4[4];
#pragma unroll
            for (int i = 0; i < 4; ++i) {
                int n = tile0 + nl0 + i;
                a[i] = (n < NN) ? *reinterpret_cast<const float4*>(X + (size_t)n * F + k4 * 4)
                                : make_float4(0.f, 0.f, 0.f, 0.f);
                h4[i] = *reinterpret_cast<const float4*>(hs0 + (nl0 + i) * PE + k4 * 4);
            }
#pragma unroll
            for (int uu = 0; uu < 4; ++uu) {
                float4 bS = *reinterpret_cast<const float4*>(Wcf + (uu * 32 + lane) * PE + k4 * 4);
                float4 bN = *reinterpret_cast<const float4*>(Wcf + (128 + uu * 32 + lane) * PE + k4 * 4);
#pragma unroll
                for (int i = 0; i < 4; ++i) {
                    float s = oacc[i][uu];
                    s = fmaf(a[i].x, bS.x, s);  s = fmaf(a[i].y, bS.y, s);
                    s = fmaf(a[i].z, bS.z, s);  s = fmaf(a[i].w, bS.w, s);
                    s = fmaf(h4[i].x, bN.x, s); s = fmaf(h4[i].y, bN.y, s);
                    s = fmaf(h4[i].z, bN.z, s); s = fmaf(h4[i].w, bN.w, s);
                    oacc[i][uu] = s;
                }
            }
        }
#pragma unroll
        for (int i = 0; i < 4; ++i) {
            int n = tile0 + nl0 + i;
            if (n < NN) {
#pragma unroll
                for (int uu = 0; uu < 4; ++uu)
                    g_H1[(size_t)n * F + uu * 32 + lane] = fmaxf(oacc[i][uu], 0.0f);
            }
        }
    } else {
        // OUT=1: warp w handles 4 nodes, dot over 128, butterfly reduce
        const int nl0 = w * 4;
        float part[4];
#pragma unroll
        for (int i = 0; i < 4; ++i) part[i] = 0.0f;
#pragma unroll
        for (int uu = 0; uu < 4; ++uu) {
            int u = uu * 32 + lane;
            float wn = __ldg(Wneigh + u);
            float ws = __ldg(Wself + u);
#pragma unroll
            for (int i = 0; i < 4; ++i) {
                int n = tile0 + nl0 + i;
                float hx = hs0[(nl0 + i) * PE + u];
                float xx = (n < NN) ? __ldg(X + (size_t)n * F + u) : 0.0f;
                part[i] = fmaf(hx, wn, fmaf(xx, ws, part[i]));
            }
        }
        float b0 = __ldg(bneigh);
#pragma unroll
        for (int off = 16; off > 0; off >>= 1)
#pragma unroll
            for (int i = 0; i < 4; ++i)
                part[i] += __shfl_xor_sync(0xffffffffu, part[i], off);
        if (lane == 0) {
#pragma unroll
            for (int i = 0; i < 4; ++i) {
                int n = tile0 + nl0 + i;
                if (n < NN) out[n] = sigm_p(part[i] + b0);
            }
        }
    }
}

extern "C" void kernel_launch(void* const* d_in, const int* in_sizes, int n_in,
                              void* d_out, int out_size) {
    const float* x       = (const float*)d_in[0];
    const int*   nbr     = (const int*)  d_in[1];
    const float* Wih1    = (const float*)d_in[2];
    const float* Whh1    = (const float*)d_in[3];
    const float* bih1    = (const float*)d_in[4];
    const float* bhh1    = (const float*)d_in[5];
    const float* Wself1  = (const float*)d_in[6];
    const float* Wneigh1 = (const float*)d_in[7];
    const float* bneigh1 = (const float*)d_in[8];
    const float* Wih2    = (const float*)d_in[9];
    const float* Whh2    = (const float*)d_in[10];
    const float* bih2    = (const float*)d_in[11];
    const float* bhh2    = (const float*)d_in[12];
    const float* Wself2  = (const float*)d_in[13];
    const float* Wneigh2 = (const float*)d_in[14];
    const float* bneigh2 = (const float*)d_in[15];
    float* out = (float*)d_out;

    const int nb = (NN + TILE - 1) / TILE;   // 313

    cudaFuncSetAttribute(proj_kernel,   cudaFuncAttributeMaxDynamicSharedMemorySize, P_SMEM_BYTES);
    cudaFuncSetAttribute(rec_kernel<1>, cudaFuncAttributeMaxDynamicSharedMemorySize, R_BYTES);
    cudaFuncSetAttribute(rec_kernel<2>, cudaFuncAttributeMaxDynamicSharedMemorySize, R_BYTES);

    proj_kernel<<<nb, NT, P_SMEM_BYTES>>>(x, 0, Wih1, bih1, bhh1);
    rec_kernel<1><<<nb, NTR, R_BYTES>>>(x, nbr, Whh1, Wself1, Wneigh1, bneigh1, nullptr);
    proj_kernel<<<nb, NT, P_SMEM_BYTES>>>(nullptr, 1, Wih2, bih2, bhh2);
    rec_kernel<2><<<nb, NTR, R_BYTES>>>(nullptr, nbr, Whh2, Wself2, Wneigh2, bneigh2, out);
}

// round 14
// speedup vs baseline: 1.4298x; 1.1585x over previous
#include <cuda_runtime.h>
#include <cuda_bf16.h>
#include <math.h>
#include <stdint.h>

// Problem constants
#define NN    20000
#define DEG   16
#define F     128
#define G4    512
#define TILE  64      // rec tile
#define TILEP 32      // proj tile (625 * 32 = 20000 exactly)
#define NT    256

// ---------------- proj kernel layout (tf32, occ 2) ----------------
#define PH    132                              // Hs float pitch
#define PWP   36                               // Wc u32 pitch (32 k-floats + pad)
#define PP_WC (TILEP*PH)                       // 4224 (u32 offset == float offset)
#define P_TOTAL (PP_WC + G4*PWP)               // 22656 words
#define P_SMEM_BYTES (P_TOTAL*4)               // 90,624 B -> 2 CTAs/SM

// ---------------- rec kernel (2-CTA cluster, bf16) layout, u32 units -----
#define PB    68      // bf16x2 pitch (u32)
#define PE    132     // fp32 pitch for epilogue weights + final-h
#define R_NB  0                                // 64*17 ints = 1088
#define R_HS  (TILE*17)                        // 1088
#define R_HSBUF (TILE*PB)                      // 4352 u32 per buffer
#define R_WC  (R_HS + 2*R_HSBUF)               // 9792
#define R_TOTAL (R_WC + 256*PB)                // 27200 u32
#define R_BYTES (R_TOTAL*4)                    // 108800 B -> 2 CTAs/SM

__device__ float g_P [(size_t)NN * G4];   // projections + bias, UNIT-MAJOR [n][unit*4+gate]
__device__ float g_H1[(size_t)NN * F];    // layer-1 output

// ---------------- helpers ----------------
__device__ __forceinline__ uint32_t f2tf(float f) {
    uint32_t u; asm("cvt.rna.tf32.f32 %0, %1;" : "=r"(u) : "f"(f)); return u;
}
__device__ __forceinline__ uint32_t packbf(float lo, float hi) {
    uint32_t r; asm("cvt.rn.bf16x2.f32 %0, %1, %2;" : "=r"(r) : "f"(hi), "f"(lo));
    return r;
}
__device__ __forceinline__ void mma8(float4& d, uint32_t a0, uint32_t a1, uint32_t a2,
                                     uint32_t a3, uint32_t b0, uint32_t b1) {
    asm volatile(
        "mma.sync.aligned.m16n8k8.row.col.f32.tf32.tf32.f32 "
        "{%0,%1,%2,%3}, {%4,%5,%6,%7}, {%8,%9}, {%0,%1,%2,%3};"
        : "+f"(d.x), "+f"(d.y), "+f"(d.z), "+f"(d.w)
        : "r"(a0), "r"(a1), "r"(a2), "r"(a3), "r"(b0), "r"(b1));
}
__device__ __forceinline__ void mma16(float4& d, uint32_t a0, uint32_t a1, uint32_t a2,
                                      uint32_t a3, uint32_t b0, uint32_t b1) {
    asm volatile(
        "mma.sync.aligned.m16n8k16.row.col.f32.bf16.bf16.f32 "
        "{%0,%1,%2,%3}, {%4,%5,%6,%7}, {%8,%9}, {%0,%1,%2,%3};"
        : "+f"(d.x), "+f"(d.y), "+f"(d.z), "+f"(d.w)
        : "r"(a0), "r"(a1), "r"(a2), "r"(a3), "r"(b0), "r"(b1));
}
__device__ __forceinline__ float sigm_f(float x) {
    float y, h = 0.5f * x;
    asm("tanh.approx.f32 %0, %1;" : "=f"(y) : "f"(h));
    return fmaf(0.5f, y, 0.5f);
}
__device__ __forceinline__ float tanh_f(float x) {
    float y; asm("tanh.approx.f32 %0, %1;" : "=f"(y) : "f"(x)); return y;
}
__device__ __forceinline__ float sigm_p(float x) { return 1.0f / (1.0f + __expf(-x)); }

__device__ __forceinline__ uint32_t ctarank() {
    uint32_t r; asm("mov.u32 %0, %%cluster_ctarank;" : "=r"(r)); return r;
}
__device__ __forceinline__ uint32_t smem_u32(const void* p) {
    uint32_t a;
    asm("{ .reg .u64 t; cvta.to.shared.u64 t, %1; cvt.u32.u64 %0, t; }" : "=r"(a) : "l"(p));
    return a;
}
__device__ __forceinline__ uint32_t mapa_u32(uint32_t addr, uint32_t rank) {
    uint32_t r; asm("mapa.shared::cluster.u32 %0, %1, %2;" : "=r"(r) : "r"(addr), "r"(rank));
    return r;
}
__device__ __forceinline__ void st_dsmem32(uint32_t addr, uint32_t v) {
    asm volatile("st.shared::cluster.u32 [%0], %1;" :: "r"(addr), "r"(v) : "memory");
}
__device__ __forceinline__ void st_dsmem64(uint32_t addr, unsigned long long v) {
    asm volatile("st.shared::cluster.u64 [%0], %1;" :: "r"(addr), "l"(v) : "memory");
}
#define CLUSTER_SYNC() do { \
    asm volatile("barrier.cluster.arrive.aligned;" ::: "memory"); \
    asm volatile("barrier.cluster.wait.aligned;" ::: "memory"); } while (0)

// ===========================================================================
// proj: g_P[n][unit*4+gate] = X[n]@Wih + bih + bhh  (tf32, M=32 tiles, occ 2)
// Staged Wih is column-permuted: Wc col q (q = wq*64 + uh*32 + gate*8 + d)
// holds original row gate*128 + wq*16 + uh*8 + d, so each thread's output
// fragment is contiguous in the unit-major P layout.
// ===========================================================================
__global__ void __launch_bounds__(NT, 2)
proj_kernel(const float* __restrict__ Xin, int useH1,
            const float* __restrict__ Wih,
            const float* __restrict__ bih, const float* __restrict__ bhh) {
    extern __shared__ float smem[];
    float* Hs = smem;                                   // [32][PH]
    uint32_t* Wc = reinterpret_cast<uint32_t*>(smem) + PP_WC;   // [512][PWP]

    const float* X = useH1 ? g_H1 : Xin;
    const int tid = threadIdx.x, lane = tid & 31, w = tid >> 5;   // w 0..7
    const int gid = lane >> 2, tig = lane & 3;
    const int tile0 = blockIdx.x * TILEP;   // exact: 625*32 = 20000

    // Stage X tile (32 rows, no bounds needed)
    for (int idx = tid; idx < TILEP * 32; idx += NT) {
        int r = idx >> 5, c4 = idx & 31;
        *reinterpret_cast<float4*>(Hs + r * PH + c4 * 4) =
            *reinterpret_cast<const float4*>(X + (size_t)(tile0 + r) * F + c4 * 4);
    }

    float4 acc[2][8];
#pragma unroll
    for (int nj = 0; nj < 8; ++nj) {
        int gate = nj & 3, uh = nj >> 2;
        int u0 = w * 16 + uh * 8 + 2 * tig;
        int oc0 = gate * 128 + u0;
        float b0 = __ldg(bih + oc0) + __ldg(bhh + oc0);
        float b1 = __ldg(bih + oc0 + 1) + __ldg(bhh + oc0 + 1);
        acc[0][nj] = make_float4(b0, b1, b0, b1);
        acc[1][nj] = make_float4(b0, b1, b0, b1);
    }

#pragma unroll 1
    for (int c = 0; c < 4; ++c) {           // K=32 chunks
        __syncthreads();
        for (int idx = tid; idx < G4 * 8; idx += NT) {
            int q = idx >> 3, k4 = idx & 7;
            int p = q & 63, wq = q >> 6;
            int gate = (p >> 3) & 3, uh = p >> 5, d = p & 7;
            int oc = gate * 128 + wq * 16 + uh * 8 + d;
            float4 v = *reinterpret_cast<const float4*>(Wih + (size_t)oc * F + c * 32 + k4 * 4);
            uint4 s;
            s.x = f2tf(v.x); s.y = f2tf(v.y); s.z = f2tf(v.z); s.w = f2tf(v.w);
            *reinterpret_cast<uint4*>(Wc + q * PWP + k4 * 4) = s;
        }
        __syncthreads();
#pragma unroll
        for (int k8 = 0; k8 < 4; ++k8) {
            uint32_t bb[8][2];
#pragma unroll
            for (int nj = 0; nj < 8; ++nj) {
                const uint32_t* bp = Wc + (w * 64 + nj * 8 + gid) * PWP + k8 * 8 + tig;
                bb[nj][0] = bp[0];
                bb[nj][1] = bp[4];
            }
#pragma unroll
            for (int mi = 0; mi < 2; ++mi) {
                const float* ap = Hs + (mi * 16 + gid) * PH + c * 32 + k8 * 8 + tig;
                uint32_t a0 = f2tf(ap[0]);
                uint32_t a1 = f2tf(ap[8 * PH]);
                uint32_t a2 = f2tf(ap[4]);
                uint32_t a3 = f2tf(ap[8 * PH + 4]);
#pragma unroll
                for (int nj = 0; nj < 8; ++nj)
                    mma8(acc[mi][nj], a0, a1, a2, a3, bb[nj][0], bb[nj][1]);
            }
        }
    }

    // Unit-major coalesced store: thread covers units u0,u0+1 per uh
#pragma unroll
    for (int mi = 0; mi < 2; ++mi) {
        int r0 = mi * 16 + gid;
        int n0 = tile0 + r0, n1 = n0 + 8;
#pragma unroll
        for (int uh = 0; uh < 2; ++uh) {
            int u = w * 16 + uh * 8 + 2 * tig;
            float4 v00 = make_float4(acc[mi][uh*4+0].x, acc[mi][uh*4+1].x,
                                     acc[mi][uh*4+2].x, acc[mi][uh*4+3].x);
            float4 v01 = make_float4(acc[mi][uh*4+0].y, acc[mi][uh*4+1].y,
                                     acc[mi][uh*4+2].y, acc[mi][uh*4+3].y);
            float4 v10 = make_float4(acc[mi][uh*4+0].z, acc[mi][uh*4+1].z,
                                     acc[mi][uh*4+2].z, acc[mi][uh*4+3].z);
            float4 v11 = make_float4(acc[mi][uh*4+0].w, acc[mi][uh*4+1].w,
                                     acc[mi][uh*4+2].w, acc[mi][uh*4+3].w);
            *reinterpret_cast<float4*>(g_P + (size_t)n0 * G4 + u * 4)       = v00;
            *reinterpret_cast<float4*>(g_P + (size_t)n0 * G4 + (u + 1) * 4) = v01;
            *reinterpret_cast<float4*>(g_P + (size_t)n1 * G4 + u * 4)       = v10;
            *reinterpret_cast<float4*>(g_P + (size_t)n1 * G4 + (u + 1) * 4) = v11;
        }
    }
}

// ===========================================================================
// rec: 2-CTA cluster, bf16 m16n8k16, Whh slice resident, 2 CTAs/SM.
// P gathered unit-major: 4 coalesced LDG.128 per mi (128B contiguous/node).
// ===========================================================================
template <int LAYER>
__global__ void __launch_bounds__(NT, 2) __cluster_dims__(2, 1, 1)
rec_kernel(const float* __restrict__ Xin, const int* __restrict__ nbr,
           const float* __restrict__ Whh, const float* __restrict__ Wself,
           const float* __restrict__ Wneigh, const float* __restrict__ bneigh,
           float* __restrict__ out) {
    extern __shared__ uint32_t smemU[];
    int*       Nb  = reinterpret_cast<int*>(smemU + R_NB);
    uint32_t*  HsB = smemU + R_HS;                 // 2 x [64][PB] bf16x2; fp32 final-h @ pitch PE
    uint32_t*  Wc  = smemU + R_WC;                 // 256 x PB bf16x2 (resident Whh slice)

    const float* X = (LAYER == 1) ? Xin : g_H1;
    const int tid = threadIdx.x, lane = tid & 31, w = tid >> 5;
    const int gid = lane >> 2, tig = lane & 3;
    const uint32_t rank = ctarank();
    const int tile0 = (blockIdx.x >> 1) * TILE;

    const uint32_t myHsByte = smem_u32(HsB);
    const uint32_t peerHsByte = mapa_u32(myHsByte, rank ^ 1u);

    // Stage neighbor indices
    for (int idx = tid; idx < TILE * DEG; idx += NT) {
        int r = idx >> 4, t = idx & 15;
        int n = tile0 + r;
        Nb[r * 17 + t] = (n < NN) ? __ldg(nbr + (size_t)n * DEG + t) : 0;
    }
    // Stage this CTA's 256-col permuted Whh slice in bf16 (ONCE).
    for (int idx = tid; idx < 256 * 32; idx += NT) {
        int q = idx >> 5, k4 = idx & 31;
        int p = q & 31, wq = q >> 5;
        int oc = (p >> 3) * 128 + (int)rank * 64 + wq * 8 + (p & 7);
        float4 v = *reinterpret_cast<const float4*>(Whh + (size_t)oc * F + k4 * 4);
        *reinterpret_cast<uint2*>(Wc + q * PB + k4 * 2) =
            make_uint2(packbf(v.x, v.y), packbf(v.z, v.w));
    }
    __syncthreads();
    CLUSTER_SYNC();

    const int u0g  = (int)rank * 64 + w * 8 + 2 * tig;  // global unit (pair base)
    const int ucolU = (int)rank * 32 + w * 4 + tig;     // bf16x2 u32 col in Hs
    const int ucolF = u0g;                              // fp32 col (final h)

    float4 cst[4];
#pragma unroll
    for (int mi = 0; mi < 4; ++mi) cst[mi] = make_float4(0.f, 0.f, 0.f, 0.f);

#pragma unroll 1
    for (int t = 0; t < DEG; ++t) {
        // Unit-major gather straight into accumulators (coalesced LDG.128,
        // overlaps the GEMM below via the scoreboard)
        float4 acc[4][4];
#pragma unroll
        for (int mi = 0; mi < 4; ++mi) {
            int r0 = mi * 16 + gid;
            const float4* Pa = reinterpret_cast<const float4*>(
                g_P + (size_t)Nb[r0 * 17 + t] * G4 + u0g * 4);
            const float4* Pb = reinterpret_cast<const float4*>(
                g_P + (size_t)Nb[(r0 + 8) * 17 + t] * G4 + u0g * 4);
            float4 A0 = __ldg(Pa), A1 = __ldg(Pa + 1);
            float4 B0 = __ldg(Pb), B1 = __ldg(Pb + 1);
            acc[mi][0] = make_float4(A0.x, A1.x, B0.x, B1.x);   // i
            acc[mi][1] = make_float4(A0.y, A1.y, B0.y, B1.y);   // f
            acc[mi][2] = make_float4(A0.z, A1.z, B0.z, B1.z);   // g
            acc[mi][3] = make_float4(A0.w, A1.w, B0.w, B1.w);   // o
        }

        if (t > 0) {
            const uint32_t* hb = HsB + ((t - 1) & 1) * R_HSBUF;
#pragma unroll 4
            for (int k16 = 0; k16 < 8; ++k16) {
                uint32_t bb[4][2];
#pragma unroll
                for (int nj = 0; nj < 4; ++nj) {
                    const uint32_t* bp = Wc + (w * 32 + nj * 8 + gid) * PB + k16 * 8 + tig;
                    bb[nj][0] = bp[0];
                    bb[nj][1] = bp[4];
                }
#pragma unroll
                for (int mi = 0; mi < 4; ++mi) {
                    const uint32_t* ap = hb + (mi * 16 + gid) * PB + k16 * 8 + tig;
                    uint32_t a0 = ap[0], a1 = ap[8 * PB], a2 = ap[4], a3 = ap[8 * PB + 4];
#pragma unroll
                    for (int nj = 0; nj < 4; ++nj)
                        mma16(acc[mi][nj], a0, a1, a2, a3, bb[nj][0], bb[nj][1]);
                }
            }
        }

        // Before overwriting with the fp32 final-h (pitch PE spans both buffers),
        // ensure the peer finished its t=15 GEMM reads of buf0.
        if (t == DEG - 1) CLUSTER_SYNC();

        uint32_t* hw = HsB + (t & 1) * R_HSBUF;
        const uint32_t remBase = peerHsByte + (((t & 1) * R_HSBUF) << 2);
#pragma unroll
        for (int mi = 0; mi < 4; ++mi) {
            int r0 = mi * 16 + gid, r1 = r0 + 8;
            float4 I = acc[mi][0], Fg = acc[mi][1], G = acc[mi][2], O = acc[mi][3];
            float4 C = cst[mi];
            float cx = fmaf(sigm_f(Fg.x), C.x, sigm_f(I.x) * tanh_f(G.x));
            float cy = fmaf(sigm_f(Fg.y), C.y, sigm_f(I.y) * tanh_f(G.y));
            float cz = fmaf(sigm_f(Fg.z), C.z, sigm_f(I.z) * tanh_f(G.z));
            float cw = fmaf(sigm_f(Fg.w), C.w, sigm_f(I.w) * tanh_f(G.w));
            cst[mi] = make_float4(cx, cy, cz, cw);
            float h00 = sigm_f(O.x) * tanh_f(cx);
            float h01 = sigm_f(O.y) * tanh_f(cy);
            float h10 = sigm_f(O.z) * tanh_f(cz);
            float h11 = sigm_f(O.w) * tanh_f(cw);

            if (t < DEG - 1) {
                uint32_t p0 = packbf(h00, h01), p1 = packbf(h10, h11);
                int o0 = r0 * PB + ucolU, o1 = r1 * PB + ucolU;
                hw[o0] = p0;
                hw[o1] = p1;
                st_dsmem32(remBase + (o0 << 2), p0);
                st_dsmem32(remBase + (o1 << 2), p1);
            } else {
                // fp32 final h at pitch PE spanning both buffers (for epilogues)
                unsigned long long q0 = (unsigned long long)__float_as_uint(h00)
                                      | ((unsigned long long)__float_as_uint(h01) << 32);
                unsigned long long q1 = (unsigned long long)__float_as_uint(h10)
                                      | ((unsigned long long)__float_as_uint(h11) << 32);
                int o0 = r0 * PE + ucolF, o1 = r1 * PE + ucolF;
                *reinterpret_cast<unsigned long long*>(HsB + o0) = q0;
                *reinterpret_cast<unsigned long long*>(HsB + o1) = q1;
                st_dsmem64(peerHsByte + (o0 << 2), q0);
                st_dsmem64(peerHsByte + (o1 << 2), q1);
            }
        }
        CLUSTER_SYNC();
    }

    // HsB = full final h in fp32, pitch PE (both halves exchanged via DSMEM)
    const float* hs0 = reinterpret_cast<const float*>(HsB);
    float* Wcf = reinterpret_cast<float*>(Wc);   // epilogue fp32 weights, pitch PE
    const int nl0 = w * 8;

    if (LAYER == 1) {
        float oacc[8][2];
#pragma unroll
        for (int uu = 0; uu < 2; ++uu) {
            float b0 = __ldg(bneigh + (int)rank * 64 + uu * 32 + lane);
#pragma unroll
            for (int i = 0; i < 8; ++i) oacc[i][uu] = b0;
        }
        // self term: X rows (global) x Wself rows rank*64..+63
        __syncthreads();
        for (int idx = tid; idx < 64 * 32; idx += NT) {
            int row = idx >> 5, k4 = idx & 31;
            *reinterpret_cast<float4*>(Wcf + row * PE + k4 * 4) =
                *reinterpret_cast<const float4*>(Wself + (size_t)((int)rank * 64 + row) * F + k4 * 4);
        }
        __syncthreads();
#pragma unroll 2
        for (int k4 = 0; k4 < 32; ++k4) {
            float4 a[8];
#pragma unroll
            for (int i = 0; i < 8; ++i) {
                int n = tile0 + nl0 + i;
                a[i] = (n < NN) ? *reinterpret_cast<const float4*>(X + (size_t)n * F + k4 * 4)
                                : make_float4(0.f, 0.f, 0.f, 0.f);
            }
#pragma unroll
            for (int uu = 0; uu < 2; ++uu) {
                float4 b = *reinterpret_cast<const float4*>(Wcf + (uu * 32 + lane) * PE + k4 * 4);
#pragma unroll
                for (int i = 0; i < 8; ++i)
                    oacc[i][uu] = fmaf(a[i].x, b.x, fmaf(a[i].y, b.y,
                                  fmaf(a[i].z, b.z, fmaf(a[i].w, b.w, oacc[i][uu]))));
            }
        }
        // neighbor term: final h (fp32) x Wneigh rows rank*64..+63
        __syncthreads();
        for (int idx = tid; idx < 64 * 32; idx += NT) {
            int row = idx >> 5, k4 = idx & 31;
            *reinterpret_cast<float4*>(Wcf + row * PE + k4 * 4) =
                *reinterpret_cast<const float4*>(Wneigh + (size_t)((int)rank * 64 + row) * F + k4 * 4);
        }
        __syncthreads();
#pragma unroll 2
        for (int k4 = 0; k4 < 32; ++k4) {
            float4 a[8];
#pragma unroll
            for (int i = 0; i < 8; ++i)
                a[i] = *reinterpret_cast<const float4*>(hs0 + (nl0 + i) * PE + k4 * 4);
#pragma unroll
            for (int uu = 0; uu < 2; ++uu) {
                float4 b = *reinterpret_cast<const float4*>(Wcf + (uu * 32 + lane) * PE + k4 * 4);
#pragma unroll
                for (int i = 0; i < 8; ++i)
                    oacc[i][uu] = fmaf(a[i].x, b.x, fmaf(a[i].y, b.y,
                                  fmaf(a[i].z, b.z, fmaf(a[i].w, b.w, oacc[i][uu]))));
            }
        }
#pragma unroll
        for (int i = 0; i < 8; ++i) {
            int n = tile0 + nl0 + i;
            if (n < NN) {
#pragma unroll
                for (int uu = 0; uu < 2; ++uu)
                    g_H1[(size_t)n * F + (int)rank * 64 + uu * 32 + lane] =
                        fmaxf(oacc[i][uu], 0.0f);
            }
        }
    } else {
        if (rank == 0) {
            float part[8];
#pragma unroll
            for (int i = 0; i < 8; ++i) part[i] = 0.0f;
#pragma unroll
            for (int uu = 0; uu < 4; ++uu) {
                int u = uu * 32 + lane;
                float wn = __ldg(Wneigh + u);
                float ws = __ldg(Wself + u);
#pragma unroll
                for (int i = 0; i < 8; ++i) {
                    int n = tile0 + nl0 + i;
                    float hx = hs0[(nl0 + i) * PE + u];
                    float xx = (n < NN) ? __ldg(X + (size_t)n * F + u) : 0.0f;
                    part[i] = fmaf(hx, wn, fmaf(xx, ws, part[i]));
                }
            }
            float b0 = __ldg(bneigh);
#pragma unroll
            for (int off = 16; off > 0; off >>= 1)
#pragma unroll
                for (int i = 0; i < 8; ++i)
                    part[i] += __shfl_xor_sync(0xffffffffu, part[i], off);
            if (lane == 0) {
#pragma unroll
                for (int i = 0; i < 8; ++i) {
                    int n = tile0 + nl0 + i;
                    if (n < NN) out[n] = sigm_p(part[i] + b0);
                }
            }
        }
    }
}

extern "C" void kernel_launch(void* const* d_in, const int* in_sizes, int n_in,
                              void* d_out, int out_size) {
    const float* x       = (const float*)d_in[0];
    const int*   nbr     = (const int*)  d_in[1];
    const float* Wih1    = (const float*)d_in[2];
    const float* Whh1    = (const float*)d_in[3];
    const float* bih1    = (const float*)d_in[4];
    const float* bhh1    = (const float*)d_in[5];
    const float* Wself1  = (const float*)d_in[6];
    const float* Wneigh1 = (const float*)d_in[7];
    const float* bneigh1 = (const float*)d_in[8];
    const float* Wih2    = (const float*)d_in[9];
    const float* Whh2    = (const float*)d_in[10];
    const float* bih2    = (const float*)d_in[11];
    const float* bhh2    = (const float*)d_in[12];
    const float* Wself2  = (const float*)d_in[13];
    const float* Wneigh2 = (const float*)d_in[14];
    const float* bneigh2 = (const float*)d_in[15];
    float* out = (float*)d_out;

    const int nbp = NN / TILEP;               // 625 proj blocks (exact)
    const int nbr_grid = ((NN + TILE - 1) / TILE) * 2;   // 626 rec CTAs

    cudaFuncSetAttribute(proj_kernel,   cudaFuncAttributeMaxDynamicSharedMemorySize, P_SMEM_BYTES);
    cudaFuncSetAttribute(rec_kernel<1>, cudaFuncAttributeMaxDynamicSharedMemorySize, R_BYTES);
    cudaFuncSetAttribute(rec_kernel<2>, cudaFuncAttributeMaxDynamicSharedMemorySize, R_BYTES);

    proj_kernel<<<nbp, NT, P_SMEM_BYTES>>>(x, 0, Wih1, bih1, bhh1);
    rec_kernel<1><<<nbr_grid, NT, R_BYTES>>>(x, nbr, Whh1, Wself1, Wneigh1, bneigh1, nullptr);
    proj_kernel<<<nbp, NT, P_SMEM_BYTES>>>(nullptr, 1, Wih2, bih2, bhh2);
    rec_kernel<2><<<nbr_grid, NT, R_BYTES>>>(nullptr, nbr, Whh2, Wself2, Wneigh2, bneigh2, out);
}